// round 14
// baseline (speedup 1.0000x reference)
#include <cuda_runtime.h>
#include <cuda_fp16.h>

#define NN 50000
#define DIM 64
#define NE 800000
#define MAXDEG 96

// ---------------- scratch (allocation-free: device globals) ----------------
__device__ __align__(16) __half g_xh [NN * DIM];        // normalized input, fp16
__device__ __align__(16) __half g_z0 [3][NN * DIM];     // dinv-scaled input per graph
__device__ __align__(16) __half g_z1 [3][NN * DIM];     // layer-1 out, pre-scaled for layer 2
__device__ __align__(16) __half g_resh[3][NN * DIM];    // layer-2 out (unscaled; norm cancels)
__device__ int   g_cnt [3][NN];
__device__ float g_dinv[3][NN];
__device__ __align__(16) unsigned short g_adjB[3][NN * MAXDEG];  // padded per-node src lists (u16)

// ---------------- kernels ----------------

// L2-normalize input rows -> g_xh (fp16). One warp per row, 2 floats per lane.
__global__ void k_l2norm_in(const float* __restrict__ x) {
    int warp = (blockIdx.x * blockDim.x + threadIdx.x) >> 5;
    int lane = threadIdx.x & 31;
    if (warp >= NN) return;
    int off = warp * DIM + lane * 2;
    float2 v = *(const float2*)(x + off);
    float s = v.x * v.x + v.y * v.y;
    #pragma unroll
    for (int o = 16; o; o >>= 1) s += __shfl_xor_sync(0xFFFFFFFFu, s, o);
    float inv = 1.0f / fmaxf(sqrtf(s), 1e-12f);
    *(__half2*)(g_xh + off) = __float22half2_rn(make_float2(v.x * inv, v.y * inv));
}

__global__ void k_zero_g(int g) {
    int i = blockIdx.x * blockDim.x + threadIdx.x;
    if (i < NN) g_cnt[g][i] = 0;
}

// Single-pass bucketed adjacency build: adj[dst*MAXDEG + cnt[dst]++] = (u16)src.
__global__ void k_fillB_g(const int* __restrict__ src, const int* __restrict__ dst, int g) {
    int e = blockIdx.x * blockDim.x + threadIdx.x;
    if (e >= NE) return;
    int dn  = __ldg(dst + e);
    int pos = atomicAdd(&g_cnt[g][dn], 1);
    if (pos < MAXDEG)                               // statistically unreachable guard
        g_adjB[g][dn * MAXDEG + pos] = (unsigned short)__ldg(src + e);
}

// Prep: dinv[n] = rsqrt(cnt[n]); z0[n] = dinv[n] * xh[n]. 8 threads per node.
__global__ void k_prep_g(int g) {
    int idx = blockIdx.x * blockDim.x + threadIdx.x;
    int n   = idx >> 3;
    if (n >= NN) return;
    int q = (idx & 7) * 8;
    int d = __ldg(&g_cnt[g][n]);
    float dv = (d > 0) ? rsqrtf((float)d) : 0.f;
    if ((idx & 7) == 0) g_dinv[g][n] = dv;

    float4 r = *(const float4*)(g_xh + n * DIM + q);
    const __half2* h = (const __half2*)&r;
    __half2 outh[4];
    #pragma unroll
    for (int k = 0; k < 4; k++) {
        float2 f = __half22float2(h[k]);
        outh[k] = __float22half2_rn(make_float2(dv * f.x, dv * f.y));
    }
    *(float4*)(g_z0[g] + n * DIM + q) = *(float4*)outh;
}

// Unweighted gather-sum aggregation. 8 threads/node, 16 B per thread, 4-edge unroll.
// layer 0: z0 -> z1, final scale dinv[n]^2 (fuses y-scale + next-layer pre-scale).
// layer 1: z1 -> resh, NO scale (row L2-normalize cancels it).
__global__ void k_agg_g(int g, int layer) {
    int idx = blockIdx.x * blockDim.x + threadIdx.x;
    int n   = idx >> 3;
    if (n >= NN) return;
    int q = (idx & 7) * 8;

    const unsigned short* adj = g_adjB[g] + n * MAXDEG;
    const __half* xin = layer ? g_z1[g]   : g_z0[g];
    __half*       yo  = layer ? g_resh[g] : g_z1[g];

    int e2 = __ldg(&g_cnt[g][n]);
    if (e2 > MAXDEG) e2 = MAXDEG;

    float2 acc[4] = { {0.f,0.f}, {0.f,0.f}, {0.f,0.f}, {0.f,0.f} };
    int j = 0;
    for (; j + 3 < e2; j += 4) {
        int s0 = __ldg(adj + j);
        int s1 = __ldg(adj + j + 1);
        int s2 = __ldg(adj + j + 2);
        int s3 = __ldg(adj + j + 3);
        float4 r0 = *(const float4*)(xin + s0 * DIM + q);
        float4 r1 = *(const float4*)(xin + s1 * DIM + q);
        float4 r2 = *(const float4*)(xin + s2 * DIM + q);
        float4 r3 = *(const float4*)(xin + s3 * DIM + q);
        const __half2* h0 = (const __half2*)&r0;
        const __half2* h1 = (const __half2*)&r1;
        const __half2* h2 = (const __half2*)&r2;
        const __half2* h3 = (const __half2*)&r3;
        #pragma unroll
        for (int k = 0; k < 4; k++) {
            float2 f0 = __half22float2(h0[k]);
            float2 f1 = __half22float2(h1[k]);
            float2 f2 = __half22float2(h2[k]);
            float2 f3 = __half22float2(h3[k]);
            acc[k].x += (f0.x + f1.x) + (f2.x + f3.x);
            acc[k].y += (f0.y + f1.y) + (f2.y + f3.y);
        }
    }
    for (; j < e2; j++) {
        int s0 = __ldg(adj + j);
        float4 r0 = *(const float4*)(xin + s0 * DIM + q);
        const __half2* h0 = (const __half2*)&r0;
        #pragma unroll
        for (int k = 0; k < 4; k++) {
            float2 f0 = __half22float2(h0[k]);
            acc[k].x += f0.x;
            acc[k].y += f0.y;
        }
    }

    float sc = 1.0f;
    if (layer == 0) {
        float dv = g_dinv[g][n];
        sc = dv * dv;
    }
    __half2 outh[4];
    #pragma unroll
    for (int k = 0; k < 4; k++)
        outh[k] = __float22half2_rn(make_float2(sc * acc[k].x, sc * acc[k].y));
    *(float4*)(yo + n * DIM + q) = *(float4*)outh;
}

// Fused: normalize each of the 3 fp16 results per row and weighted-combine (fp32 out).
__global__ void k_combine(const float* __restrict__ alpha, float* __restrict__ out) {
    int warp = (blockIdx.x * blockDim.x + threadIdx.x) >> 5;
    int lane = threadIdx.x & 31;
    if (warp >= NN) return;

    float a0 = alpha[0], a1 = alpha[1], a2 = alpha[2];
    float m  = fmaxf(a0, fmaxf(a1, a2));
    float e0 = expf(a0 - m), e1 = expf(a1 - m), e2 = expf(a2 - m);
    float s3 = e0 + e1 + e2;
    float w0 = fmaxf(e0 / s3, 1e-4f);
    float w1 = fmaxf(e1 / s3, 1e-4f);
    float w2 = fmaxf(e2 / s3, 1e-4f);
    float ws = w0 + w1 + w2;
    w0 /= ws; w1 /= ws; w2 /= ws;

    int off = warp * DIM + lane * 2;
    float2 va = __half22float2(*(const __half2*)(g_resh[0] + off));
    float2 vb = __half22float2(*(const __half2*)(g_resh[1] + off));
    float2 vc = __half22float2(*(const __half2*)(g_resh[2] + off));
    float sa = va.x * va.x + va.y * va.y;
    float sb = vb.x * vb.x + vb.y * vb.y;
    float sc = vc.x * vc.x + vc.y * vc.y;
    #pragma unroll
    for (int o = 16; o; o >>= 1) {
        sa += __shfl_xor_sync(0xFFFFFFFFu, sa, o);
        sb += __shfl_xor_sync(0xFFFFFFFFu, sb, o);
        sc += __shfl_xor_sync(0xFFFFFFFFu, sc, o);
    }
    float ia = 1.0f / fmaxf(sqrtf(sa), 1e-12f);
    float ib = 1.0f / fmaxf(sqrtf(sb), 1e-12f);
    float ic = 1.0f / fmaxf(sqrtf(sc), 1e-12f);

    float2 r;
    r.x = w0 * va.x * ia + w1 * vb.x * ib + w2 * vc.x * ic;
    r.y = w0 * va.y * ia + w1 * vb.y * ib + w2 * vc.y * ic;
    *(float2*)(out + off) = r;
}

// ---------------- launch ----------------
extern "C" void kernel_launch(void* const* d_in, const int* in_sizes, int n_in,
                              void* d_out, int out_size) {
    const float* x     = (const float*)d_in[0];
    const float* alpha = (const float*)d_in[1];
    const int*   srcs[3] = { (const int*)d_in[2], (const int*)d_in[3], (const int*)d_in[4] };
    float* out = (float*)d_out;

    // One-time host-side stream/event setup (no device memory involved).
    static cudaStream_t st[3];
    static cudaEvent_t  evFork, evX, evDone[3];
    static bool inited = false;
    if (!inited) {
        for (int g = 0; g < 3; g++)
            cudaStreamCreateWithFlags(&st[g], cudaStreamNonBlocking);
        cudaEventCreateWithFlags(&evFork, cudaEventDisableTiming);
        cudaEventCreateWithFlags(&evX,    cudaEventDisableTiming);
        for (int g = 0; g < 3; g++)
            cudaEventCreateWithFlags(&evDone[g], cudaEventDisableTiming);
        inited = true;
    }

    const int T = 256;
    const int gRows  = (NN * 32 + T - 1) / T;
    const int gNode  = (NN + T - 1) / T;
    const int gEdge  = (NE + T - 1) / T;
    const int gNode8 = (NN * 8 + T - 1) / T;

    // Fork per-graph pipelines off the main stream.
    cudaEventRecord(evFork, 0);
    for (int g = 0; g < 3; g++)
        cudaStreamWaitEvent(st[g], evFork, 0);

    // Main stream: normalize input (overlaps adjacency builds).
    k_l2norm_in<<<gRows, T>>>(x);
    cudaEventRecord(evX, 0);

    for (int g = 0; g < 3; g++) {
        const int* src = srcs[g];
        const int* dst = srcs[g] + NE;
        k_zero_g <<<gNode, T, 0, st[g]>>>(g);
        k_fillB_g<<<gEdge, T, 0, st[g]>>>(src, dst, g);
        cudaStreamWaitEvent(st[g], evX, 0);            // prep needs g_xh
        k_prep_g <<<gNode8, T, 0, st[g]>>>(g);         // dinv + z0 = dinv*xh
        k_agg_g  <<<gNode8, T, 0, st[g]>>>(g, 0);      // z0 -> z1 (scale dinv^2)
        k_agg_g  <<<gNode8, T, 0, st[g]>>>(g, 1);      // z1 -> resh (no scale)
        cudaEventRecord(evDone[g], st[g]);
    }

    for (int g = 0; g < 3; g++)
        cudaStreamWaitEvent(0, evDone[g], 0);
    k_combine<<<gRows, T>>>(alpha, out);
}

// round 15
// speedup vs baseline: 1.0259x; 1.0259x over previous
#include <cuda_runtime.h>
#include <cuda_fp16.h>

#define NN 50000
#define DIM 64
#define NE 800000
#define MAXDEG 96

// ---------------- scratch (allocation-free: device globals) ----------------
// NOTE: g_cnt is zero-initialized at module load and re-zeroed at the tail of
// k_combine each launch, so every launch starts with zero counts.
__device__ __align__(16) __half g_xh [NN * DIM];        // normalized input, fp16
__device__ __align__(16) __half g_z0 [3][NN * DIM];     // dinv-scaled input per graph
__device__ __align__(16) __half g_z1 [3][NN * DIM];     // layer-1 out, pre-scaled for layer 2
__device__ __align__(16) __half g_resh[3][NN * DIM];    // layer-2 out (unscaled; norm cancels)
__device__ int   g_cnt [3][NN];
__device__ float g_dinv[3][NN];
__device__ int   g_adjB[3][NN * MAXDEG];                // padded per-node src lists

// ---------------- kernels ----------------

// L2-normalize input rows -> g_xh (fp16). One warp per row, 2 floats per lane.
__global__ void k_l2norm_in(const float* __restrict__ x) {
    int warp = (blockIdx.x * blockDim.x + threadIdx.x) >> 5;
    int lane = threadIdx.x & 31;
    if (warp >= NN) return;
    int off = warp * DIM + lane * 2;
    float2 v = *(const float2*)(x + off);
    float s = v.x * v.x + v.y * v.y;
    #pragma unroll
    for (int o = 16; o; o >>= 1) s += __shfl_xor_sync(0xFFFFFFFFu, s, o);
    float inv = 1.0f / fmaxf(sqrtf(s), 1e-12f);
    *(__half2*)(g_xh + off) = __float22half2_rn(make_float2(v.x * inv, v.y * inv));
}

// Single-pass bucketed adjacency build: adj[dst*MAXDEG + cnt[dst]++] = src.
__global__ void k_fillB_g(const int* __restrict__ src, const int* __restrict__ dst, int g) {
    int e = blockIdx.x * blockDim.x + threadIdx.x;
    if (e >= NE) return;
    int dn  = __ldg(dst + e);
    int pos = atomicAdd(&g_cnt[g][dn], 1);
    if (pos < MAXDEG)                               // statistically unreachable guard
        g_adjB[g][dn * MAXDEG + pos] = __ldg(src + e);
}

// Prep: dinv[n] = rsqrt(cnt[n]); z0[n] = dinv[n] * xh[n]. 8 threads per node.
__global__ void k_prep_g(int g) {
    int idx = blockIdx.x * blockDim.x + threadIdx.x;
    int n   = idx >> 3;
    if (n >= NN) return;
    int q = (idx & 7) * 8;
    int d = __ldg(&g_cnt[g][n]);
    float dv = (d > 0) ? rsqrtf((float)d) : 0.f;
    if ((idx & 7) == 0) g_dinv[g][n] = dv;

    float4 r = *(const float4*)(g_xh + n * DIM + q);
    const __half2* h = (const __half2*)&r;
    __half2 outh[4];
    #pragma unroll
    for (int k = 0; k < 4; k++) {
        float2 f = __half22float2(h[k]);
        outh[k] = __float22half2_rn(make_float2(dv * f.x, dv * f.y));
    }
    *(float4*)(g_z0[g] + n * DIM + q) = *(float4*)outh;
}

// Unweighted gather-sum aggregation. 8 threads/node, 16 B per thread, 4-edge unroll.
// layer 0: z0 -> z1, final scale dinv[n]^2 (fuses y-scale + next-layer pre-scale).
// layer 1: z1 -> resh, NO scale (row L2-normalize cancels it).
__global__ void k_agg_g(int g, int layer) {
    int idx = blockIdx.x * blockDim.x + threadIdx.x;
    int n   = idx >> 3;
    if (n >= NN) return;
    int q = (idx & 7) * 8;

    const int*    adj = g_adjB[g] + n * MAXDEG;
    const __half* xin = layer ? g_z1[g]   : g_z0[g];
    __half*       yo  = layer ? g_resh[g] : g_z1[g];

    int e2 = __ldg(&g_cnt[g][n]);
    if (e2 > MAXDEG) e2 = MAXDEG;

    float2 acc[4] = { {0.f,0.f}, {0.f,0.f}, {0.f,0.f}, {0.f,0.f} };
    int j = 0;
    for (; j + 3 < e2; j += 4) {
        int s0 = __ldg(adj + j);
        int s1 = __ldg(adj + j + 1);
        int s2 = __ldg(adj + j + 2);
        int s3 = __ldg(adj + j + 3);
        float4 r0 = *(const float4*)(xin + s0 * DIM + q);
        float4 r1 = *(const float4*)(xin + s1 * DIM + q);
        float4 r2 = *(const float4*)(xin + s2 * DIM + q);
        float4 r3 = *(const float4*)(xin + s3 * DIM + q);
        const __half2* h0 = (const __half2*)&r0;
        const __half2* h1 = (const __half2*)&r1;
        const __half2* h2 = (const __half2*)&r2;
        const __half2* h3 = (const __half2*)&r3;
        #pragma unroll
        for (int k = 0; k < 4; k++) {
            float2 f0 = __half22float2(h0[k]);
            float2 f1 = __half22float2(h1[k]);
            float2 f2 = __half22float2(h2[k]);
            float2 f3 = __half22float2(h3[k]);
            acc[k].x += (f0.x + f1.x) + (f2.x + f3.x);
            acc[k].y += (f0.y + f1.y) + (f2.y + f3.y);
        }
    }
    for (; j < e2; j++) {
        int s0 = __ldg(adj + j);
        float4 r0 = *(const float4*)(xin + s0 * DIM + q);
        const __half2* h0 = (const __half2*)&r0;
        #pragma unroll
        for (int k = 0; k < 4; k++) {
            float2 f0 = __half22float2(h0[k]);
            acc[k].x += f0.x;
            acc[k].y += f0.y;
        }
    }

    float sc = 1.0f;
    if (layer == 0) {
        float dv = g_dinv[g][n];
        sc = dv * dv;
    }
    __half2 outh[4];
    #pragma unroll
    for (int k = 0; k < 4; k++)
        outh[k] = __float22half2_rn(make_float2(sc * acc[k].x, sc * acc[k].y));
    *(float4*)(yo + n * DIM + q) = *(float4*)outh;
}

// Fused: normalize each of the 3 fp16 results per row, weighted-combine (fp32 out),
// and re-zero g_cnt for the next launch (keeps zeroing off the critical path).
__global__ void k_combine(const float* __restrict__ alpha, float* __restrict__ out) {
    int gid  = blockIdx.x * blockDim.x + threadIdx.x;

    // Piggybacked count zeroing for the next launch (3*NN ints << total threads).
    if (gid < 3 * NN) ((int*)g_cnt)[gid] = 0;

    int warp = gid >> 5;
    int lane = threadIdx.x & 31;
    if (warp >= NN) return;

    float a0 = alpha[0], a1 = alpha[1], a2 = alpha[2];
    float m  = fmaxf(a0, fmaxf(a1, a2));
    float e0 = expf(a0 - m), e1 = expf(a1 - m), e2 = expf(a2 - m);
    float s3 = e0 + e1 + e2;
    float w0 = fmaxf(e0 / s3, 1e-4f);
    float w1 = fmaxf(e1 / s3, 1e-4f);
    float w2 = fmaxf(e2 / s3, 1e-4f);
    float ws = w0 + w1 + w2;
    w0 /= ws; w1 /= ws; w2 /= ws;

    int off = warp * DIM + lane * 2;
    float2 va = __half22float2(*(const __half2*)(g_resh[0] + off));
    float2 vb = __half22float2(*(const __half2*)(g_resh[1] + off));
    float2 vc = __half22float2(*(const __half2*)(g_resh[2] + off));
    float sa = va.x * va.x + va.y * va.y;
    float sb = vb.x * vb.x + vb.y * vb.y;
    float sc = vc.x * vc.x + vc.y * vc.y;
    #pragma unroll
    for (int o = 16; o; o >>= 1) {
        sa += __shfl_xor_sync(0xFFFFFFFFu, sa, o);
        sb += __shfl_xor_sync(0xFFFFFFFFu, sb, o);
        sc += __shfl_xor_sync(0xFFFFFFFFu, sc, o);
    }
    float ia = 1.0f / fmaxf(sqrtf(sa), 1e-12f);
    float ib = 1.0f / fmaxf(sqrtf(sb), 1e-12f);
    float ic = 1.0f / fmaxf(sqrtf(sc), 1e-12f);

    float2 r;
    r.x = w0 * va.x * ia + w1 * vb.x * ib + w2 * vc.x * ic;
    r.y = w0 * va.y * ia + w1 * vb.y * ib + w2 * vc.y * ic;
    *(float2*)(out + off) = r;
}

// ---------------- launch ----------------
extern "C" void kernel_launch(void* const* d_in, const int* in_sizes, int n_in,
                              void* d_out, int out_size) {
    const float* x     = (const float*)d_in[0];
    const float* alpha = (const float*)d_in[1];
    const int*   srcs[3] = { (const int*)d_in[2], (const int*)d_in[3], (const int*)d_in[4] };
    float* out = (float*)d_out;

    // One-time host-side stream/event setup (no device memory involved).
    static cudaStream_t st[3];
    static cudaEvent_t  evFork, evX, evDone[3];
    static bool inited = false;
    if (!inited) {
        for (int g = 0; g < 3; g++)
            cudaStreamCreateWithFlags(&st[g], cudaStreamNonBlocking);
        cudaEventCreateWithFlags(&evFork, cudaEventDisableTiming);
        cudaEventCreateWithFlags(&evX,    cudaEventDisableTiming);
        for (int g = 0; g < 3; g++)
            cudaEventCreateWithFlags(&evDone[g], cudaEventDisableTiming);
        inited = true;
    }

    const int T = 256;
    const int gRows  = (NN * 32 + T - 1) / T;
    const int gEdge  = (NE + T - 1) / T;
    const int gNode8 = (NN * 8 + T - 1) / T;

    // Fork per-graph pipelines off the main stream.
    cudaEventRecord(evFork, 0);
    for (int g = 0; g < 3; g++)
        cudaStreamWaitEvent(st[g], evFork, 0);

    // Main stream: normalize input (overlaps adjacency builds).
    k_l2norm_in<<<gRows, T>>>(x);
    cudaEventRecord(evX, 0);

    for (int g = 0; g < 3; g++) {
        const int* src = srcs[g];
        const int* dst = srcs[g] + NE;
        k_fillB_g<<<gEdge, T, 0, st[g]>>>(src, dst, g);   // counts pre-zeroed by prior combine
        cudaStreamWaitEvent(st[g], evX, 0);               // prep needs g_xh
        k_prep_g <<<gNode8, T, 0, st[g]>>>(g);            // dinv + z0 = dinv*xh
        k_agg_g  <<<gNode8, T, 0, st[g]>>>(g, 0);         // z0 -> z1 (scale dinv^2)
        k_agg_g  <<<gNode8, T, 0, st[g]>>>(g, 1);         // z1 -> resh (no scale)
        cudaEventRecord(evDone[g], st[g]);
    }

    for (int g = 0; g < 3; g++)
        cudaStreamWaitEvent(0, evDone[g], 0);
    k_combine<<<gRows, T>>>(alpha, out);
}

// round 16
// speedup vs baseline: 1.1101x; 1.0820x over previous
#include <cuda_runtime.h>
#include <cuda_fp16.h>

#define NN 50000
#define DIM 64
#define NE 800000
#define MAXDEG 96

// ---------------- scratch (allocation-free: device globals) ----------------
// NOTE: g_cnt is zero-initialized at module load and re-zeroed at the tail of
// k_combine each launch, so every launch starts with zero counts.
__device__ __align__(16) __half g_xh [NN * DIM];        // normalized input, fp16
__device__ __align__(16) __half g_z0 [3][NN * DIM];     // dinv-scaled input per graph
__device__ __align__(16) __half g_z1 [3][NN * DIM];     // layer-1 out, pre-scaled for layer 2
__device__ __align__(16) __half g_resh[3][NN * DIM];    // layer-2 out (unscaled; norm cancels)
__device__ int   g_cnt [3][NN];
__device__ float g_dinv[3][NN];
__device__ int   g_adjB[3][NN * MAXDEG];                // padded per-node src lists

// ---------------- kernels ----------------

// L2-normalize input rows -> g_xh (fp16). One warp per row, 2 floats per lane.
__global__ void k_l2norm_in(const float* __restrict__ x) {
    int warp = (blockIdx.x * blockDim.x + threadIdx.x) >> 5;
    int lane = threadIdx.x & 31;
    if (warp >= NN) return;
    int off = warp * DIM + lane * 2;
    float2 v = *(const float2*)(x + off);
    float s = v.x * v.x + v.y * v.y;
    #pragma unroll
    for (int o = 16; o; o >>= 1) s += __shfl_xor_sync(0xFFFFFFFFu, s, o);
    float inv = 1.0f / fmaxf(sqrtf(s), 1e-12f);
    *(__half2*)(g_xh + off) = __float22half2_rn(make_float2(v.x * inv, v.y * inv));
}

// Single-pass bucketed adjacency build: adj[dst*MAXDEG + cnt[dst]++] = src.
__global__ void k_fillB_g(const int* __restrict__ src, const int* __restrict__ dst, int g) {
    int e = blockIdx.x * blockDim.x + threadIdx.x;
    if (e >= NE) return;
    int dn  = __ldg(dst + e);
    int pos = atomicAdd(&g_cnt[g][dn], 1);
    if (pos < MAXDEG)                               // statistically unreachable guard
        g_adjB[g][dn * MAXDEG + pos] = __ldg(src + e);
}

// Prep: dinv[n] = rsqrt(cnt[n]); z0[n] = dinv[n] * xh[n]. 8 threads per node.
__global__ void k_prep_g(int g) {
    int idx = blockIdx.x * blockDim.x + threadIdx.x;
    int n   = idx >> 3;
    if (n >= NN) return;
    int q = (idx & 7) * 8;
    int d = __ldg(&g_cnt[g][n]);
    float dv = (d > 0) ? rsqrtf((float)d) : 0.f;
    if ((idx & 7) == 0) g_dinv[g][n] = dv;

    float4 r = *(const float4*)(g_xh + n * DIM + q);
    const __half2* h = (const __half2*)&r;
    __half2 outh[4];
    #pragma unroll
    for (int k = 0; k < 4; k++) {
        float2 f = __half22float2(h[k]);
        outh[k] = __float22half2_rn(make_float2(dv * f.x, dv * f.y));
    }
    *(float4*)(g_z0[g] + n * DIM + q) = *(float4*)outh;
}

// Unweighted gather-sum aggregation. 8 threads/node, 16 B per thread, 4-edge unroll.
// fp16 pairwise pre-add (HADD2) halves the conversion+FADD count; pair sums are
// accumulated in fp32.
// layer 0: z0 -> z1, final scale dinv[n]^2; layer 1: z1 -> resh, no scale.
__global__ void k_agg_g(int g, int layer) {
    int idx = blockIdx.x * blockDim.x + threadIdx.x;
    int n   = idx >> 3;
    if (n >= NN) return;
    int q = (idx & 7) * 8;

    const int*    adj = g_adjB[g] + n * MAXDEG;
    const __half* xin = layer ? g_z1[g]   : g_z0[g];
    __half*       yo  = layer ? g_resh[g] : g_z1[g];

    int e2 = __ldg(&g_cnt[g][n]);
    if (e2 > MAXDEG) e2 = MAXDEG;

    float2 acc[4] = { {0.f,0.f}, {0.f,0.f}, {0.f,0.f}, {0.f,0.f} };
    int j = 0;
    for (; j + 3 < e2; j += 4) {
        int s0 = __ldg(adj + j);
        int s1 = __ldg(adj + j + 1);
        int s2 = __ldg(adj + j + 2);
        int s3 = __ldg(adj + j + 3);
        float4 r0 = *(const float4*)(xin + s0 * DIM + q);
        float4 r1 = *(const float4*)(xin + s1 * DIM + q);
        float4 r2 = *(const float4*)(xin + s2 * DIM + q);
        float4 r3 = *(const float4*)(xin + s3 * DIM + q);
        const __half2* h0 = (const __half2*)&r0;
        const __half2* h1 = (const __half2*)&r1;
        const __half2* h2 = (const __half2*)&r2;
        const __half2* h3 = (const __half2*)&r3;
        #pragma unroll
        for (int k = 0; k < 4; k++) {
            __half2 p01 = __hadd2(h0[k], h1[k]);       // fp16 pairwise pre-add
            __half2 p23 = __hadd2(h2[k], h3[k]);
            float2 f01 = __half22float2(p01);
            float2 f23 = __half22float2(p23);
            acc[k].x += f01.x + f23.x;
            acc[k].y += f01.y + f23.y;
        }
    }
    if (j + 1 < e2) {                                  // 2-edge remainder, same trick
        int s0 = __ldg(adj + j);
        int s1 = __ldg(adj + j + 1);
        float4 r0 = *(const float4*)(xin + s0 * DIM + q);
        float4 r1 = *(const float4*)(xin + s1 * DIM + q);
        const __half2* h0 = (const __half2*)&r0;
        const __half2* h1 = (const __half2*)&r1;
        #pragma unroll
        for (int k = 0; k < 4; k++) {
            float2 f = __half22float2(__hadd2(h0[k], h1[k]));
            acc[k].x += f.x;
            acc[k].y += f.y;
        }
        j += 2;
    }
    if (j < e2) {                                      // final odd edge
        int s0 = __ldg(adj + j);
        float4 r0 = *(const float4*)(xin + s0 * DIM + q);
        const __half2* h0 = (const __half2*)&r0;
        #pragma unroll
        for (int k = 0; k < 4; k++) {
            float2 f0 = __half22float2(h0[k]);
            acc[k].x += f0.x;
            acc[k].y += f0.y;
        }
    }

    float sc = 1.0f;
    if (layer == 0) {
        float dv = g_dinv[g][n];
        sc = dv * dv;
    }
    __half2 outh[4];
    #pragma unroll
    for (int k = 0; k < 4; k++)
        outh[k] = __float22half2_rn(make_float2(sc * acc[k].x, sc * acc[k].y));
    *(float4*)(yo + n * DIM + q) = *(float4*)outh;
}

// Fused: normalize each of the 3 fp16 results per row, weighted-combine (fp32 out),
// and re-zero g_cnt for the next launch (keeps zeroing off the critical path).
__global__ void k_combine(const float* __restrict__ alpha, float* __restrict__ out) {
    int gid  = blockIdx.x * blockDim.x + threadIdx.x;

    // Piggybacked count zeroing for the next launch (3*NN ints << total threads).
    if (gid < 3 * NN) ((int*)g_cnt)[gid] = 0;

    int warp = gid >> 5;
    int lane = threadIdx.x & 31;
    if (warp >= NN) return;

    float a0 = alpha[0], a1 = alpha[1], a2 = alpha[2];
    float m  = fmaxf(a0, fmaxf(a1, a2));
    float e0 = expf(a0 - m), e1 = expf(a1 - m), e2 = expf(a2 - m);
    float s3 = e0 + e1 + e2;
    float w0 = fmaxf(e0 / s3, 1e-4f);
    float w1 = fmaxf(e1 / s3, 1e-4f);
    float w2 = fmaxf(e2 / s3, 1e-4f);
    float ws = w0 + w1 + w2;
    w0 /= ws; w1 /= ws; w2 /= ws;

    int off = warp * DIM + lane * 2;
    float2 va = __half22float2(*(const __half2*)(g_resh[0] + off));
    float2 vb = __half22float2(*(const __half2*)(g_resh[1] + off));
    float2 vc = __half22float2(*(const __half2*)(g_resh[2] + off));
    float sa = va.x * va.x + va.y * va.y;
    float sb = vb.x * vb.x + vb.y * vb.y;
    float sc = vc.x * vc.x + vc.y * vc.y;
    #pragma unroll
    for (int o = 16; o; o >>= 1) {
        sa += __shfl_xor_sync(0xFFFFFFFFu, sa, o);
        sb += __shfl_xor_sync(0xFFFFFFFFu, sb, o);
        sc += __shfl_xor_sync(0xFFFFFFFFu, sc, o);
    }
    float ia = 1.0f / fmaxf(sqrtf(sa), 1e-12f);
    float ib = 1.0f / fmaxf(sqrtf(sb), 1e-12f);
    float ic = 1.0f / fmaxf(sqrtf(sc), 1e-12f);

    float2 r;
    r.x = w0 * va.x * ia + w1 * vb.x * ib + w2 * vc.x * ic;
    r.y = w0 * va.y * ia + w1 * vb.y * ib + w2 * vc.y * ic;
    *(float2*)(out + off) = r;
}

// ---------------- launch ----------------
extern "C" void kernel_launch(void* const* d_in, const int* in_sizes, int n_in,
                              void* d_out, int out_size) {
    const float* x     = (const float*)d_in[0];
    const float* alpha = (const float*)d_in[1];
    const int*   srcs[3] = { (const int*)d_in[2], (const int*)d_in[3], (const int*)d_in[4] };
    float* out = (float*)d_out;

    // One-time host-side stream/event setup (no device memory involved).
    static cudaStream_t st[3];
    static cudaEvent_t  evFork, evX, evDone[3];
    static bool inited = false;
    if (!inited) {
        for (int g = 0; g < 3; g++)
            cudaStreamCreateWithFlags(&st[g], cudaStreamNonBlocking);
        cudaEventCreateWithFlags(&evFork, cudaEventDisableTiming);
        cudaEventCreateWithFlags(&evX,    cudaEventDisableTiming);
        for (int g = 0; g < 3; g++)
            cudaEventCreateWithFlags(&evDone[g], cudaEventDisableTiming);
        inited = true;
    }

    const int T = 256;
    const int gRows  = (NN * 32 + T - 1) / T;
    const int gEdge  = (NE + T - 1) / T;
    const int gNode8 = (NN * 8 + T - 1) / T;

    // Fork per-graph pipelines off the main stream.
    cudaEventRecord(evFork, 0);
    for (int g = 0; g < 3; g++)
        cudaStreamWaitEvent(st[g], evFork, 0);

    // Main stream: normalize input (overlaps adjacency builds).
    k_l2norm_in<<<gRows, T>>>(x);
    cudaEventRecord(evX, 0);

    for (int g = 0; g < 3; g++) {
        const int* src = srcs[g];
        const int* dst = srcs[g] + NE;
        k_fillB_g<<<gEdge, T, 0, st[g]>>>(src, dst, g);   // counts pre-zeroed by prior combine
        cudaStreamWaitEvent(st[g], evX, 0);               // prep needs g_xh
        k_prep_g <<<gNode8, T, 0, st[g]>>>(g);            // dinv + z0 = dinv*xh
        k_agg_g  <<<gNode8, T, 0, st[g]>>>(g, 0);         // z0 -> z1 (scale dinv^2)
        k_agg_g  <<<gNode8, T, 0, st[g]>>>(g, 1);         // z1 -> resh (no scale)
        cudaEventRecord(evDone[g], st[g]);
    }

    for (int g = 0; g < 3; g++)
        cudaStreamWaitEvent(0, evDone[g], 0);
    k_combine<<<gRows, T>>>(alpha, out);
}